// round 16
// baseline (speedup 1.0000x reference)
#include <cuda_runtime.h>
#include <cuda_fp16.h>
#include <math.h>

#define B_   128
#define T_   256
#define H_   512
#define G4_  2048   // 4*H

// ---------------- scratch (device globals; no allocation allowed) -------------
__device__ uint4    g_xf[2097152];      // x as fp16 A-frags [t][ks][rt][lane]
__device__ uint4    g_if[4194304];      // layer-0 out frags [dir][t][ks][rt][lane]
__device__ uint4    g_hfh[32768];       // h ping-pong frags [pp][dir][ks][rt][lane]
__device__ float4   g_XP[1048576];      // XP ring: [blin*4+wl][slot(8)][q(8)*32+lane]
__device__ unsigned g_arrive[4];        // cumulative, zero-init  [dir*2+bhalf]
__device__ unsigned g_gen[4];           // cumulative, zero-init

// ---------------- helpers ----------------------------------------------------
__device__ __forceinline__ void mma16(float* c, const uint4& a, const uint2& b) {
    asm volatile(
        "mma.sync.aligned.m16n8k16.row.col.f32.f16.f16.f32 "
        "{%0,%1,%2,%3}, {%4,%5,%6,%7}, {%8,%9}, {%0,%1,%2,%3};\n"
        : "+f"(c[0]), "+f"(c[1]), "+f"(c[2]), "+f"(c[3])
        : "r"(a.x), "r"(a.y), "r"(a.z), "r"(a.w), "r"(b.x), "r"(b.y));
}

__device__ __forceinline__ unsigned packh2(float lo, float hi) {
    __half2 h = __halves2half2(__float2half_rn(lo), __float2half_rn(hi));
    return *reinterpret_cast<unsigned*>(&h);
}

__device__ __forceinline__ float sigm(float x) {
    return 1.f / (1.f + __expf(-x));
}
__device__ __forceinline__ float tanh_(float x) {
    float e = __expf(2.f * x);
    return 1.f - 2.f / (e + 1.f);
}

__device__ __forceinline__ void cp_async16(unsigned smem_addr, const void* gptr) {
    asm volatile("cp.async.cg.shared.global [%0], [%1], 16;\n"
                 :: "r"(smem_addr), "l"(gptr));
}
__device__ __forceinline__ void cp_commit() {
    asm volatile("cp.async.commit_group;\n");
}
template<int N> __device__ __forceinline__ void cp_wait() {
    asm volatile("cp.async.wait_group %0;\n" :: "n"(N));
}

// ---------------- x -> fp16 A-fragment conversion -----------------------------
__global__ void __launch_bounds__(128) conv_kernel(const float* __restrict__ x)
{
    const int t = blockIdx.x, bhalf = blockIdx.y;
    const int tid = threadIdx.x, lane = tid & 31, warp = tid >> 5;
    const int rt = bhalf * 4 + warp;
    const int r  = rt * 16 + (lane >> 2);
    const int k0 = 2 * (lane & 3);
    const float* xr0 = x + ((size_t)r * 256 + t) * 512;
    const float* xr1 = x + ((size_t)(r + 8) * 256 + t) * 512;
    uint4* dst = g_xf + (size_t)t * 8192 + rt * 32 + lane;
    #pragma unroll 4
    for (int ks = 0; ks < 32; ks++) {
        int kk = ks * 16 + k0;
        float2 a0 = *reinterpret_cast<const float2*>(xr0 + kk);
        float2 a1 = *reinterpret_cast<const float2*>(xr1 + kk);
        float2 a2 = *reinterpret_cast<const float2*>(xr0 + kk + 8);
        float2 a3 = *reinterpret_cast<const float2*>(xr1 + kk + 8);
        uint4 fr;
        fr.x = packh2(a0.x, a0.y);
        fr.y = packh2(a1.x, a1.y);
        fr.z = packh2(a2.x, a2.y);
        fr.w = packh2(a3.x, a3.y);
        dst[ks * 256] = fr;
    }
}

// ---------------- warp-specialized persistent scan (decoupled) ----------------
// grid (32, 2, 2) x 256 threads. Warps 0-3 (h-warps): recurrence chain with
// named-barrier grid sync. Warps 4-7 (x-warps): FREE-RUNNING input projection
// up to 8 steps ahead into a gmem ring; warp-pair (same wl) handshake via
// per-wl smem counters. No per-step __syncthreads.
// smem: Whb 64K | Wxb 64K | hstage 64K = 192 KB.
#define SCAN_SMEM (65536 * 3)

__global__ void __launch_bounds__(256, 1) scan_kernel(
    const float* __restrict__ Wh_all, const float* __restrict__ Wx_all,
    const float* __restrict__ bias, int layer, int last, float* __restrict__ out)
{
    extern __shared__ char smbase[];
    uint2* Whb = reinterpret_cast<uint2*>(smbase);
    uint2* Wxb = reinterpret_cast<uint2*>(smbase + 65536);
    uint4* hst = reinterpret_cast<uint4*>(smbase + 131072);   // [ks(32)][tl(128)]

    __shared__ volatile unsigned s_prod[4], s_cons[4];
    __shared__ unsigned s_genbase;

    const int tid  = threadIdx.x;
    const int lane = tid & 31, warp = tid >> 5;
    const bool is_h = warp < 4;
    const int wl = warp & 3;
    const int tl = (wl << 5) | lane;
    const int slice = blockIdx.x;
    const int bhalf = blockIdx.y;
    const int dir   = blockIdx.z;
    const int grp   = dir * 2 + bhalf;
    const int blin  = grp * 32 + slice;
    const int j0    = slice * 16;
    const int rt    = bhalf * 4 + wl;
    const float* Wh = Wh_all + (size_t)(layer * 2 + dir) * H_ * G4_;
    const float* Wx = Wx_all + (size_t)(layer * 2 + dir) * H_ * G4_;
    const float* bs = bias   + (layer * 2 + dir) * G4_;
    const uint4* xfrag = layer ? (g_if + (size_t)dir * 2097152) : g_xf;

    if (tid < 4) { s_prod[tid] = 0u; s_cons[tid] = 0u; }
    if (tid == 0) s_genbase = *((volatile unsigned*)&g_gen[grp]);

    // prepack Wh and Wx B-fragments (m16n8k16) -- all 256 threads
    for (int idx = tid; idx < 8192; idx += 256) {
        int l  = idx & 31;
        int q  = idx >> 5;
        int nt = q & 1, g = (q >> 1) & 3, ks = q >> 3;
        int k0 = ks * 16 + 2 * (l & 3);
        int n  = g * 512 + j0 + nt * 8 + (l >> 2);
        Whb[idx] = make_uint2(
            packh2(Wh[(size_t)k0 * 2048 + n], Wh[(size_t)(k0 + 1) * 2048 + n]),
            packh2(Wh[(size_t)(k0 + 8) * 2048 + n], Wh[(size_t)(k0 + 9) * 2048 + n]));
        Wxb[idx] = make_uint2(
            packh2(Wx[(size_t)k0 * 2048 + n], Wx[(size_t)(k0 + 1) * 2048 + n]),
            packh2(Wx[(size_t)(k0 + 8) * 2048 + n], Wx[(size_t)(k0 + 9) * 2048 + n]));
    }
    __syncthreads();
    const unsigned gen_base = s_genbase;

    const int row_base = rt * 16 + (lane >> 2);
    const int u2 = 2 * (lane & 3);
    const unsigned hs_addr =
        (unsigned)__cvta_generic_to_shared(hst) + (unsigned)tl * 16;

    if (is_h) {
        // =================== consumer: recurrence serial chain ===============
        float creg[2][4] = {{0.f,0.f,0.f,0.f},{0.f,0.f,0.f,0.f}};
        int p = 0;
        #pragma unroll 1
        for (int s = 0; s < 256; s++) {
            const int t = (dir == 0) ? s : (255 - s);

            // wait for XP(s) from paired x-warp (runs ~8 ahead: rarely blocks)
            while ((int)(s_prod[wl]) <= s) {}
            __threadfence_block();   // acquire: order LDGs after flag
            float4 xpv[8];
            const float4* xsrc = g_XP
                + ((size_t)(blin * 4 + wl) * 8 + (unsigned)(s & 7)) * 256 + lane;
            #pragma unroll
            for (int q = 0; q < 8; q++) xpv[q] = xsrc[q * 32];

            float acc[4][2][4];
            #pragma unroll
            for (int g = 0; g < 4; g++)
                #pragma unroll
                for (int nt = 0; nt < 2; nt++)
                    #pragma unroll
                    for (int k = 0; k < 4; k++) acc[g][nt][k] = 0.f;

            if (s > 0) {
                #pragma unroll
                for (int g4 = 0; g4 < 4; g4++) {
                    if      (g4 == 0) cp_wait<3>();
                    else if (g4 == 1) cp_wait<2>();
                    else if (g4 == 2) cp_wait<1>();
                    else              cp_wait<0>();
                    #pragma unroll
                    for (int k8 = 0; k8 < 8; k8++) {
                        int ks = g4 * 8 + k8;
                        uint4 a = hst[ks * 128 + tl];
                        #pragma unroll
                        for (int g = 0; g < 4; g++)
                            #pragma unroll
                            for (int nt = 0; nt < 2; nt++)
                                mma16(acc[g][nt], a,
                                      Whb[((ks * 4 + g) * 2 + nt) * 32 + lane]);
                    }
                }
            }

            // LSTM pointwise epilogue
            float hn[2][4];
            #pragma unroll
            for (int nt = 0; nt < 2; nt++)
                #pragma unroll
                for (int k = 0; k < 4; k++) {
                    const float* pi = &xpv[0 * 2 + nt].x;
                    const float* pf = &xpv[1 * 2 + nt].x;
                    const float* pg = &xpv[2 * 2 + nt].x;
                    const float* po = &xpv[3 * 2 + nt].x;
                    float i_ = sigm(acc[0][nt][k] + pi[k]);
                    float f_ = sigm(acc[1][nt][k] + pf[k]);
                    float gg = tanh_(acc[2][nt][k] + pg[k]);
                    float o_ = sigm(acc[3][nt][k] + po[k]);
                    float cn = f_ * creg[nt][k] + i_ * gg;
                    creg[nt][k] = cn;
                    hn[nt][k] = o_ * tanh_(cn);
                }

            // release ring slot (all lanes done with xpv)
            __syncwarp();
            if (lane == 0) s_cons[wl] = (unsigned)(s + 1);

            uint4 fr;
            fr.x = packh2(hn[0][0], hn[0][1]);
            fr.y = packh2(hn[0][2], hn[0][3]);
            fr.z = packh2(hn[1][0], hn[1][1]);
            fr.w = packh2(hn[1][2], hn[1][3]);

            if (s < 255)
                g_hfh[((1 - p) * 2 + dir) * 8192 + slice * 256 + rt * 32 + lane] = fr;

            if (!last) {
                g_if[(size_t)dir * 2097152 + (size_t)t * 8192
                     + slice * 256 + rt * 32 + lane] = fr;
            } else {
                #pragma unroll
                for (int nt = 0; nt < 2; nt++)
                    #pragma unroll
                    for (int rr = 0; rr < 2; rr++) {
                        int r = row_base + rr * 8;
                        int u = j0 + nt * 8 + u2;
                        *reinterpret_cast<float2*>(
                            out + ((size_t)r * 256 + t) * 1024 + dir * 512 + u) =
                            make_float2(hn[nt][rr * 2], hn[nt][rr * 2 + 1]);
                    }
            }

            if (s < 255) {
                // h-warps-only barrier: all publishes done before arrive
                asm volatile("bar.sync 1, 128;" ::: "memory");
                if (tid == 0) {
                    __threadfence();
                    unsigned old = atomicAdd(&g_arrive[grp], 1u);
                    if ((old & 31u) == 31u) {
                        __threadfence();
                        atomicAdd(&g_gen[grp], 1u);
                    }
                }
                {
                    unsigned target = gen_base + (unsigned)(s + 1);
                    while ((int)(*((volatile unsigned*)&g_gen[grp]) - target) < 0) {}
                }
                const uint4* hsrc = g_hfh + ((1 - p) * 2 + dir) * 8192
                                  + bhalf * 128 + tl;
                #pragma unroll
                for (int g4 = 0; g4 < 4; g4++) {
                    #pragma unroll
                    for (int k8 = 0; k8 < 8; k8++) {
                        int ks = g4 * 8 + k8;
                        cp_async16(hs_addr + (unsigned)ks * 2048, hsrc + ks * 256);
                    }
                    cp_commit();
                }
            }
            p ^= 1;
        }
    } else {
        // =================== producer: free-running input projection =========
        float2 bias2[4][2];
        #pragma unroll
        for (int g = 0; g < 4; g++)
            #pragma unroll
            for (int nt = 0; nt < 2; nt++)
                bias2[g][nt] = *reinterpret_cast<const float2*>(
                    bs + g * 512 + j0 + nt * 8 + u2);

        #pragma unroll 1
        for (int sx = 0; sx < 256; sx++) {
            const int tx = (dir == 0) ? sx : (255 - sx);

            // ring space (depth 8)
            while (sx - (int)s_cons[wl] >= 8) {}

            const uint4* xs = xfrag + (size_t)tx * 8192 + rt * 32 + lane;
            float pvacc[4][2][4];
            uint4 xb[8];
            #pragma unroll
            for (int i = 0; i < 8; i++) xb[i] = xs[i * 256];
            #pragma unroll
            for (int g = 0; g < 4; g++)
                #pragma unroll
                for (int nt = 0; nt < 2; nt++) {
                    pvacc[g][nt][0] = bias2[g][nt].x;
                    pvacc[g][nt][1] = bias2[g][nt].y;
                    pvacc[g][nt][2] = bias2[g][nt].x;
                    pvacc[g][nt][3] = bias2[g][nt].y;
                }
            #pragma unroll
            for (int ks = 0; ks < 32; ks++) {
                uint4 a = xb[ks & 7];
                if (ks < 24) xb[ks & 7] = xs[(ks + 8) * 256];
                #pragma unroll
                for (int g = 0; g < 4; g++)
                    #pragma unroll
                    for (int nt = 0; nt < 2; nt++)
                        mma16(pvacc[g][nt], a,
                              Wxb[((ks * 4 + g) * 2 + nt) * 32 + lane]);
            }

            float4* dst = g_XP
                + ((size_t)(blin * 4 + wl) * 8 + (unsigned)(sx & 7)) * 256 + lane;
            #pragma unroll
            for (int g = 0; g < 4; g++)
                #pragma unroll
                for (int nt = 0; nt < 2; nt++)
                    dst[(g * 2 + nt) * 32] =
                        make_float4(pvacc[g][nt][0], pvacc[g][nt][1],
                                    pvacc[g][nt][2], pvacc[g][nt][3]);

            __syncwarp();              // all lanes' stores issued
            __threadfence_block();     // publish to same-CTA consumers
            if (lane == 0) s_prod[wl] = (unsigned)(sx + 1);
        }
    }
}

// ---------------- launch ------------------------------------------------------
extern "C" void kernel_launch(void* const* d_in, const int* in_sizes, int n_in,
                              void* d_out, int out_size)
{
    (void)in_sizes; (void)n_in; (void)out_size;
    const float* x  = (const float*)d_in[0];
    const float* Wx = (const float*)d_in[1];
    const float* Wh = (const float*)d_in[2];
    const float* b  = (const float*)d_in[3];
    float* out = (float*)d_out;

    // idempotent, capture-legal; no static guards (harness rule)
    cudaFuncSetAttribute(scan_kernel,
                         cudaFuncAttributeMaxDynamicSharedMemorySize, SCAN_SMEM);

    dim3 gc(256, 2);
    dim3 gs(32, 2, 2);

    conv_kernel<<<gc, 128>>>(x);
    scan_kernel<<<gs, 256, SCAN_SMEM>>>(Wh, Wx, b, 0, 0, out);
    scan_kernel<<<gs, 256, SCAN_SMEM>>>(Wh, Wx, b, 1, 1, out);
}

// round 17
// speedup vs baseline: 1.0030x; 1.0030x over previous
#include <cuda_runtime.h>
#include <cuda_fp16.h>
#include <math.h>

#define B_   128
#define T_   256
#define H_   512
#define G4_  2048   // 4*H

// ---------------- scratch (device globals; no allocation allowed) -------------
__device__ uint4    g_xf[2097152];      // x as fp16 A-frags [t][ks][rt][lane]
__device__ uint4    g_if[4194304];      // layer-0 out frags [dir][t][ks][rt][lane]
__device__ uint4    g_hfh[32768];       // h ping-pong frags [pp][dir][ks][rt][lane]
__device__ float4   g_XP[1048576];      // XP ring: [blin*4+wl][slot(8)][q(8)*32+lane]
__device__ unsigned g_arrive[4];        // cumulative, zero-init  [dir*2+bhalf]
__device__ unsigned g_gen[4];           // cumulative, zero-init

// ---------------- helpers ----------------------------------------------------
__device__ __forceinline__ void mma16(float* c, const uint4& a, const uint2& b) {
    asm volatile(
        "mma.sync.aligned.m16n8k16.row.col.f32.f16.f16.f32 "
        "{%0,%1,%2,%3}, {%4,%5,%6,%7}, {%8,%9}, {%0,%1,%2,%3};\n"
        : "+f"(c[0]), "+f"(c[1]), "+f"(c[2]), "+f"(c[3])
        : "r"(a.x), "r"(a.y), "r"(a.z), "r"(a.w), "r"(b.x), "r"(b.y));
}

__device__ __forceinline__ unsigned packh2(float lo, float hi) {
    __half2 h = __halves2half2(__float2half_rn(lo), __float2half_rn(hi));
    return *reinterpret_cast<unsigned*>(&h);
}

__device__ __forceinline__ float sigm(float x) {
    return 1.f / (1.f + __expf(-x));
}
__device__ __forceinline__ float tanh_(float x) {
    float e = __expf(2.f * x);
    return 1.f - 2.f / (e + 1.f);
}

__device__ __forceinline__ void cp_async16(unsigned smem_addr, const void* gptr) {
    asm volatile("cp.async.cg.shared.global [%0], [%1], 16;\n"
                 :: "r"(smem_addr), "l"(gptr));
}
__device__ __forceinline__ void cp_commit() {
    asm volatile("cp.async.commit_group;\n");
}
template<int N> __device__ __forceinline__ void cp_wait() {
    asm volatile("cp.async.wait_group %0;\n" :: "n"(N));
}

// ---------------- x -> fp16 A-fragment conversion -----------------------------
__global__ void __launch_bounds__(128) conv_kernel(const float* __restrict__ x)
{
    const int t = blockIdx.x, bhalf = blockIdx.y;
    const int tid = threadIdx.x, lane = tid & 31, warp = tid >> 5;
    const int rt = bhalf * 4 + warp;
    const int r  = rt * 16 + (lane >> 2);
    const int k0 = 2 * (lane & 3);
    const float* xr0 = x + ((size_t)r * 256 + t) * 512;
    const float* xr1 = x + ((size_t)(r + 8) * 256 + t) * 512;
    uint4* dst = g_xf + (size_t)t * 8192 + rt * 32 + lane;
    #pragma unroll 4
    for (int ks = 0; ks < 32; ks++) {
        int kk = ks * 16 + k0;
        float2 a0 = *reinterpret_cast<const float2*>(xr0 + kk);
        float2 a1 = *reinterpret_cast<const float2*>(xr1 + kk);
        float2 a2 = *reinterpret_cast<const float2*>(xr0 + kk + 8);
        float2 a3 = *reinterpret_cast<const float2*>(xr1 + kk + 8);
        uint4 fr;
        fr.x = packh2(a0.x, a0.y);
        fr.y = packh2(a1.x, a1.y);
        fr.z = packh2(a2.x, a2.y);
        fr.w = packh2(a3.x, a3.y);
        dst[ks * 256] = fr;
    }
}

// ---------------- warp-specialized persistent scan (decoupled, free waits) ----
// grid (32, 2, 2) x 256 threads. Warps 0-3 (h-warps): recurrence chain.
// Warps 4-7 (x-warps): free-running input projection up to 8 steps ahead into
// a gmem ring; pairwise handshake via per-wl smem counters.
// ALL non-critical waits are issue-free: producer backoff = __nanosleep,
// barrier waiters park in bar.sync while only tid 0 polls.
// smem: Whb 64K | Wxb 64K | hstage 64K = 192 KB.
#define SCAN_SMEM (65536 * 3)

__global__ void __launch_bounds__(256, 1) scan_kernel(
    const float* __restrict__ Wh_all, const float* __restrict__ Wx_all,
    const float* __restrict__ bias, int layer, int last, float* __restrict__ out)
{
    extern __shared__ char smbase[];
    uint2* Whb = reinterpret_cast<uint2*>(smbase);
    uint2* Wxb = reinterpret_cast<uint2*>(smbase + 65536);
    uint4* hst = reinterpret_cast<uint4*>(smbase + 131072);   // [ks(32)][tl(128)]

    __shared__ volatile unsigned s_prod[4], s_cons[4];
    __shared__ unsigned s_genbase;

    const int tid  = threadIdx.x;
    const int lane = tid & 31, warp = tid >> 5;
    const bool is_h = warp < 4;
    const int wl = warp & 3;
    const int tl = (wl << 5) | lane;
    const int slice = blockIdx.x;
    const int bhalf = blockIdx.y;
    const int dir   = blockIdx.z;
    const int grp   = dir * 2 + bhalf;
    const int blin  = grp * 32 + slice;
    const int j0    = slice * 16;
    const int rt    = bhalf * 4 + wl;
    const float* Wh = Wh_all + (size_t)(layer * 2 + dir) * H_ * G4_;
    const float* Wx = Wx_all + (size_t)(layer * 2 + dir) * H_ * G4_;
    const float* bs = bias   + (layer * 2 + dir) * G4_;
    const uint4* xfrag = layer ? (g_if + (size_t)dir * 2097152) : g_xf;

    if (tid < 4) { s_prod[tid] = 0u; s_cons[tid] = 0u; }
    if (tid == 0) s_genbase = *((volatile unsigned*)&g_gen[grp]);

    // prepack Wh and Wx B-fragments (m16n8k16) -- all 256 threads
    for (int idx = tid; idx < 8192; idx += 256) {
        int l  = idx & 31;
        int q  = idx >> 5;
        int nt = q & 1, g = (q >> 1) & 3, ks = q >> 3;
        int k0 = ks * 16 + 2 * (l & 3);
        int n  = g * 512 + j0 + nt * 8 + (l >> 2);
        Whb[idx] = make_uint2(
            packh2(Wh[(size_t)k0 * 2048 + n], Wh[(size_t)(k0 + 1) * 2048 + n]),
            packh2(Wh[(size_t)(k0 + 8) * 2048 + n], Wh[(size_t)(k0 + 9) * 2048 + n]));
        Wxb[idx] = make_uint2(
            packh2(Wx[(size_t)k0 * 2048 + n], Wx[(size_t)(k0 + 1) * 2048 + n]),
            packh2(Wx[(size_t)(k0 + 8) * 2048 + n], Wx[(size_t)(k0 + 9) * 2048 + n]));
    }
    __syncthreads();
    const unsigned gen_base = s_genbase;

    const int row_base = rt * 16 + (lane >> 2);
    const int u2 = 2 * (lane & 3);
    const unsigned hs_addr =
        (unsigned)__cvta_generic_to_shared(hst) + (unsigned)tl * 16;

    if (is_h) {
        // =================== consumer: recurrence serial chain ===============
        float creg[2][4] = {{0.f,0.f,0.f,0.f},{0.f,0.f,0.f,0.f}};
        int p = 0;
        #pragma unroll 1
        for (int s = 0; s < 256; s++) {
            const int t = (dir == 0) ? s : (255 - s);

            // wait for XP(s) from paired x-warp (producer ~8 ahead: brief)
            while ((int)(s_prod[wl]) <= s) {}
            __threadfence_block();   // acquire: order LDGs after flag
            float4 xpv[8];
            const float4* xsrc = g_XP
                + ((size_t)(blin * 4 + wl) * 8 + (unsigned)(s & 7)) * 256 + lane;
            #pragma unroll
            for (int q = 0; q < 8; q++) xpv[q] = xsrc[q * 32];

            float acc[4][2][4];
            #pragma unroll
            for (int g = 0; g < 4; g++)
                #pragma unroll
                for (int nt = 0; nt < 2; nt++)
                    #pragma unroll
                    for (int k = 0; k < 4; k++) acc[g][nt][k] = 0.f;

            if (s > 0) {
                #pragma unroll
                for (int g4 = 0; g4 < 4; g4++) {
                    if      (g4 == 0) cp_wait<3>();
                    else if (g4 == 1) cp_wait<2>();
                    else if (g4 == 2) cp_wait<1>();
                    else              cp_wait<0>();
                    #pragma unroll
                    for (int k8 = 0; k8 < 8; k8++) {
                        int ks = g4 * 8 + k8;
                        uint4 a = hst[ks * 128 + tl];
                        #pragma unroll
                        for (int g = 0; g < 4; g++)
                            #pragma unroll
                            for (int nt = 0; nt < 2; nt++)
                                mma16(acc[g][nt], a,
                                      Whb[((ks * 4 + g) * 2 + nt) * 32 + lane]);
                    }
                }
            }

            // LSTM pointwise epilogue
            float hn[2][4];
            #pragma unroll
            for (int nt = 0; nt < 2; nt++)
                #pragma unroll
                for (int k = 0; k < 4; k++) {
                    const float* pi = &xpv[0 * 2 + nt].x;
                    const float* pf = &xpv[1 * 2 + nt].x;
                    const float* pg = &xpv[2 * 2 + nt].x;
                    const float* po = &xpv[3 * 2 + nt].x;
                    float i_ = sigm(acc[0][nt][k] + pi[k]);
                    float f_ = sigm(acc[1][nt][k] + pf[k]);
                    float gg = tanh_(acc[2][nt][k] + pg[k]);
                    float o_ = sigm(acc[3][nt][k] + po[k]);
                    float cn = f_ * creg[nt][k] + i_ * gg;
                    creg[nt][k] = cn;
                    hn[nt][k] = o_ * tanh_(cn);
                }

            // release ring slot (all lanes done with xpv)
            __syncwarp();
            if (lane == 0) s_cons[wl] = (unsigned)(s + 1);

            uint4 fr;
            fr.x = packh2(hn[0][0], hn[0][1]);
            fr.y = packh2(hn[0][2], hn[0][3]);
            fr.z = packh2(hn[1][0], hn[1][1]);
            fr.w = packh2(hn[1][2], hn[1][3]);

            if (s < 255)
                g_hfh[((1 - p) * 2 + dir) * 8192 + slice * 256 + rt * 32 + lane] = fr;

            if (!last) {
                g_if[(size_t)dir * 2097152 + (size_t)t * 8192
                     + slice * 256 + rt * 32 + lane] = fr;
            } else {
                #pragma unroll
                for (int nt = 0; nt < 2; nt++)
                    #pragma unroll
                    for (int rr = 0; rr < 2; rr++) {
                        int r = row_base + rr * 8;
                        int u = j0 + nt * 8 + u2;
                        *reinterpret_cast<float2*>(
                            out + ((size_t)r * 256 + t) * 1024 + dir * 512 + u) =
                            make_float2(hn[nt][rr * 2], hn[nt][rr * 2 + 1]);
                    }
            }

            if (s < 255) {
                // all h-warps' publishes done before arrive
                asm volatile("bar.sync 1, 128;" ::: "memory");
                if (tid == 0) {
                    __threadfence();
                    unsigned old = atomicAdd(&g_arrive[grp], 1u);
                    if ((old & 31u) == 31u) {
                        __threadfence();
                        atomicAdd(&g_gen[grp], 1u);
                    }
                    // leader-only poll; 127 peers park issue-free in bar below
                    unsigned target = gen_base + (unsigned)(s + 1);
                    while ((int)(*((volatile unsigned*)&g_gen[grp]) - target) < 0) {}
                }
                asm volatile("bar.sync 1, 128;" ::: "memory");

                const uint4* hsrc = g_hfh + ((1 - p) * 2 + dir) * 8192
                                  + bhalf * 128 + tl;
                #pragma unroll
                for (int g4 = 0; g4 < 4; g4++) {
                    #pragma unroll
                    for (int k8 = 0; k8 < 8; k8++) {
                        int ks = g4 * 8 + k8;
                        cp_async16(hs_addr + (unsigned)ks * 2048, hsrc + ks * 256);
                    }
                    cp_commit();
                }
            }
            p ^= 1;
        }
    } else {
        // =================== producer: free-running input projection =========
        float2 bias2[4][2];
        #pragma unroll
        for (int g = 0; g < 4; g++)
            #pragma unroll
            for (int nt = 0; nt < 2; nt++)
                bias2[g][nt] = *reinterpret_cast<const float2*>(
                    bs + g * 512 + j0 + nt * 8 + u2);

        #pragma unroll 1
        for (int sx = 0; sx < 256; sx++) {
            const int tx = (dir == 0) ? sx : (255 - sx);

            // ring space (depth 8) -- BACKOFF: do not steal issue slots from
            // the h-warp on this SMSP (this hot spin was the R16 regression)
            while (sx - (int)s_cons[wl] >= 8) __nanosleep(200);

            const uint4* xs = xfrag + (size_t)tx * 8192 + rt * 32 + lane;
            float pvacc[4][2][4];
            uint4 xb[8];
            #pragma unroll
            for (int i = 0; i < 8; i++) xb[i] = xs[i * 256];
            #pragma unroll
            for (int g = 0; g < 4; g++)
                #pragma unroll
                for (int nt = 0; nt < 2; nt++) {
                    pvacc[g][nt][0] = bias2[g][nt].x;
                    pvacc[g][nt][1] = bias2[g][nt].y;
                    pvacc[g][nt][2] = bias2[g][nt].x;
                    pvacc[g][nt][3] = bias2[g][nt].y;
                }
            #pragma unroll
            for (int ks = 0; ks < 32; ks++) {
                uint4 a = xb[ks & 7];
                if (ks < 24) xb[ks & 7] = xs[(ks + 8) * 256];
                #pragma unroll
                for (int g = 0; g < 4; g++)
                    #pragma unroll
                    for (int nt = 0; nt < 2; nt++)
                        mma16(pvacc[g][nt], a,
                              Wxb[((ks * 4 + g) * 2 + nt) * 32 + lane]);
            }

            float4* dst = g_XP
                + ((size_t)(blin * 4 + wl) * 8 + (unsigned)(sx & 7)) * 256 + lane;
            #pragma unroll
            for (int g = 0; g < 4; g++)
                #pragma unroll
                for (int nt = 0; nt < 2; nt++)
                    dst[(g * 2 + nt) * 32] =
                        make_float4(pvacc[g][nt][0], pvacc[g][nt][1],
                                    pvacc[g][nt][2], pvacc[g][nt][3]);

            __syncwarp();              // all lanes' stores issued
            __threadfence_block();     // publish to same-CTA consumers
            if (lane == 0) s_prod[wl] = (unsigned)(sx + 1);
        }
    }
}

// ---------------- launch ------------------------------------------------------
extern "C" void kernel_launch(void* const* d_in, const int* in_sizes, int n_in,
                              void* d_out, int out_size)
{
    (void)in_sizes; (void)n_in; (void)out_size;
    const float* x  = (const float*)d_in[0];
    const float* Wx = (const float*)d_in[1];
    const float* Wh = (const float*)d_in[2];
    const float* b  = (const float*)d_in[3];
    float* out = (float*)d_out;

    // idempotent, capture-legal; no static guards (harness rule)
    cudaFuncSetAttribute(scan_kernel,
                         cudaFuncAttributeMaxDynamicSharedMemorySize, SCAN_SMEM);

    dim3 gc(256, 2);
    dim3 gs(32, 2, 2);

    conv_kernel<<<gc, 128>>>(x);
    scan_kernel<<<gs, 256, SCAN_SMEM>>>(Wh, Wx, b, 0, 0, out);
    scan_kernel<<<gs, 256, SCAN_SMEM>>>(Wh, Wx, b, 1, 1, out);
}